// round 10
// baseline (speedup 1.0000x reference)
#include <cuda_runtime.h>

// filtfilt(butter(4,0.2)) over 512 rows x 48000 fp32.
//
// R9 measured (NTH=256, WARM=48, CHUNK=49): 61.5us, issue 76.3%, fma 43.8%,
// DRAM 33%, occ 45% -> ISSUE-BOUND. Warm-up fraction was 48/97 = 49% waste.
// R10: NTH=128, CHUNK=95, WARM=40 -> useful fraction 70%, total filter-phase
// instructions x0.70. 16 warps/SM still saturate an FMA-dominated loop.
//
// Correctness model (unchanged):
//  1. scale divide/multiply cancels (linear pipeline).
//  2. overlap-save: 40-sample zero-state warm-up, pole decay 0.7955^40 ~ 1e-4
//     -> predicted rel_err ~3e-5 (measured 4.9e-6 at WARM=48).
//  3. seg-0 forward / seg-3 backward exact (zero-masked warm-in = reference
//     zero-state init).

#define T_LEN   48000
#define PAD     15
#define TP      (T_LEN + 2 * PAD)     // 48030
#define NTH     128
#define NSEG    4
#define SEG_OUT 12000                 // output samples per block
#define WARM    40                    // 0.7955^40 ~ 1.1e-4
#define LEN     (SEG_OUT + 2 * WARM)  // window = 12080 floats = 47.19 KB
#define CHUNK_F 95                    // odd -> conflict-free; 127*95 >= LEN-WARM
#define CHUNK_B 95                    // odd; 127*95 >= SEG_OUT

// FIR b (a0=1), symmetric
#define B0f 0.004824343357716228f
#define B1f 0.019297373430864913f
#define B2f 0.02894606014629737f
// Negated IIR feedback: yn = f - a1*y1 - a2*y2 - a3*y3 - a4*y4
#define NA1 ( 2.369513007182038f)
#define NA2 (-2.3139884144006455f)
#define NA3 ( 1.0546654058785672f)
#define NA4 (-0.18737949236818502f)

// Loop-carried chain = final fma only (4 cyc/sample); earlier fmas use older state.
__device__ __forceinline__ float iir_step(float f, float y1, float y2, float y3, float y4) {
    float c = fmaf(NA4, y4, f);
    c = fmaf(NA3, y3, c);
    c = fmaf(NA2, y2, c);
    return fmaf(NA1, y1, c);
}
__device__ __forceinline__ float fir5(float xc, float m1, float m2, float m3, float m4) {
    return fmaf(B0f, xc + m4, fmaf(B1f, m1 + m3, B2f * m2));
}

__global__ void __launch_bounds__(NTH, 4)
filtfilt_kernel(const float* __restrict__ x, float* __restrict__ out)
{
    extern __shared__ float s[];            // LEN floats
    const int seg = blockIdx.x;             // 0..3
    const int row = blockIdx.y;
    const float* __restrict__ xr = x + (size_t)row * T_LEN;
    float* __restrict__ yr = out + (size_t)row * T_LEN;
    const int tid  = threadIdx.x;
    const int o0   = seg * SEG_OUT;         // first output sample of this block
    const int base = PAD + o0 - WARM;       // padded-domain index of s[0]

    // ---- Load window: s[i] = padded_x[base+i] (0 outside [0,TP)) ----
    // Bulk covers g in [PAD, PAD+T_LEN); WARM%4==0, o0%4==0, PAD-base ≡ 0 mod 4
    // keep every bulk pointer float4-aligned.
    {
        const int lo = max(0, PAD - base);                  // 40 for seg 0, else 0
        const int hi = min(LEN, PAD + T_LEN - base);        // 12040 for seg 3, else LEN
        const float4* __restrict__ src4 = (const float4*)(xr + (base + lo - PAD));
        float4* __restrict__ dst4 = (float4*)(s + lo);
        const int n4 = (hi - lo) >> 2;
        for (int j4 = tid; j4 < n4; j4 += NTH)
            dst4[j4] = src4[j4];
        // Edge elements (seg 0 first 40 / seg 3 last 40): odd reflection pad.
        // left pad (g in [0,PAD)):       v = 2*x[0]   - x[PAD-1-g]
        // right pad (g in [PAD+T, TP)):  v = 2*x[T-1] - x[2T+PAD-3-g]
        for (int i = tid; i < LEN - (hi - lo); i += NTH) {
            int ii = (i < lo) ? i : (hi + i - lo);          // indices outside [lo,hi)
            int g = base + ii;
            float v = 0.f;
            if ((unsigned)g < (unsigned)TP) {
                if (g < PAD)               v = 2.f * xr[0] - xr[PAD - 1 - g];
                else if (g >= PAD + T_LEN) v = 2.f * xr[T_LEN - 1] - xr[2 * T_LEN + PAD - 3 - g];
                else                       v = xr[g - PAD];
            }
            s[ii] = v;
        }
    }
    __syncthreads();

    // ==================== FORWARD (in place) ====================
    // Targets [WARM, LEN): segment output region + right margin for bwd warm-up.
    {
        const int c0 = min(WARM + tid * CHUNK_F, LEN);
        const int c1 = min(c0 + CHUNK_F, LEN);
        float m1 = 0.f, m2 = 0.f, m3 = 0.f, m4 = 0.f;
        float y1 = 0.f, y2 = 0.f, y3 = 0.f, y4 = 0.f;
#pragma unroll 4
        for (int t = c0 - WARM; t < c0; ++t) {            // read-only, in [0,LEN)
            float xc = s[t];
            float f  = fir5(xc, m1, m2, m3, m4);
            float yn = iir_step(f, y1, y2, y3, y4);
            m4 = m3; m3 = m2; m2 = m1; m1 = xc;
            y4 = y3; y3 = y2; y2 = y1; y1 = yn;
        }
        __syncthreads();
#pragma unroll 4
        for (int t = c0; t < c1; ++t) {                   // own chunk: RAW-safe in place
            float xc = s[t];
            float f  = fir5(xc, m1, m2, m3, m4);
            float yn = iir_step(f, y1, y2, y3, y4);
            s[t] = yn;
            m4 = m3; m3 = m2; m2 = m1; m1 = xc;
            y4 = y3; y3 = y2; y2 = y1; y1 = yn;
        }
    }
    __syncthreads();

    // ==================== BACKWARD (in place) ====================
    // Targets [WARM, WARM+SEG_OUT); warm-up reads forward output in the right
    // margin; past the padded end (ilim) masked to 0 = reference zero state.
    {
        const int b0 = min(WARM + tid * CHUNK_B, WARM + SEG_OUT);
        const int b1 = min(b0 + CHUNK_B, WARM + SEG_OUT);
        const int ilim = TP - base;
        float m1 = 0.f, m2 = 0.f, m3 = 0.f, m4 = 0.f;
        float y1 = 0.f, y2 = 0.f, y3 = 0.f, y4 = 0.f;
#pragma unroll 4
        for (int t = b1 + WARM - 1; t >= b1; --t) {       // t < b1+WARM <= LEN
            float xc = (t < ilim) ? s[t] : 0.f;
            float f  = fir5(xc, m1, m2, m3, m4);
            float vn = iir_step(f, y1, y2, y3, y4);
            m4 = m3; m3 = m2; m2 = m1; m1 = xc;
            y4 = y3; y3 = y2; y2 = y1; y1 = vn;
        }
        __syncthreads();
#pragma unroll 4
        for (int t = b1 - 1; t >= b0; --t) {
            float xc = s[t];
            float f  = fir5(xc, m1, m2, m3, m4);
            float vn = iir_step(f, y1, y2, y3, y4);
            s[t] = vn;
            m4 = m3; m3 = m2; m2 = m1; m1 = xc;
            y4 = y3; y3 = y2; y2 = y1; y1 = vn;
        }
    }
    __syncthreads();

    // ---- Output: out[o0+j] = s[WARM+j]; both sides 16B-aligned ----
    {
        const float4* __restrict__ sb4 = (const float4*)(s + WARM);
        float4* __restrict__ yr4 = (float4*)(yr + o0);
        for (int j4 = tid; j4 < SEG_OUT / 4; j4 += NTH)
            yr4[j4] = sb4[j4];
    }
}

extern "C" void kernel_launch(void* const* d_in, const int* in_sizes, int n_in,
                              void* d_out, int out_size)
{
    const float* x = (const float*)d_in[0];
    float* out = (float*)d_out;
    const int rows = in_sizes[0] / T_LEN;            // 512
    const int smem_bytes = LEN * (int)sizeof(float); // 48320

    cudaFuncSetAttribute(filtfilt_kernel,
                         cudaFuncAttributeMaxDynamicSharedMemorySize,
                         smem_bytes);
    dim3 grid(NSEG, rows);
    filtfilt_kernel<<<grid, NTH, smem_bytes>>>(x, out);
}